// round 16
// baseline (speedup 1.0000x reference)
#include <cuda_runtime.h>
#include <cuda_bf16.h>
#include <cuda_fp16.h>
#include <cstdint>

#define NN   100000
#define EE   1000000
#define HID  32
#define NH1  8
#define OUTC 40
#define NEGS 0.2f

// ================= device scratch =================
__device__ __align__(16) __half g_h1h[(size_t)NN * 256];   // layer1 messages, fp16
__device__ __align__(16) __half g_x2h[(size_t)NN * 256];   // relu(layer1 out), fp16
__device__ __align__(16) float g_as1[NN * NH1];
__device__ __align__(16) float g_ad1[NN * NH1];
__device__ __align__(16) __half g_h2h[NN * HID];           // layer2 messages, fp16
__device__ __align__(16) float g_as2[NN];
__device__ __align__(16) float g_ad2[NN];
__device__ __align__(16) __half g_w1h[32768];              // W1 fp16, tile layout [ct][n][k]
__device__ __align__(16) __half g_w2hi[8192];              // W2 split fp16, [n][k] layout
__device__ __align__(16) __half g_w2lo[8192];
__device__ int g_cnt[NN];
__device__ int g_rowptr[NN + 1];
__device__ int g_cursor[NN];
__device__ int g_col[EE];
__device__ int g_bsum[128];
__device__ int g_boff[128];

__device__ __forceinline__ float leaky(float x) { return x > 0.f ? x : NEGS * x; }

__device__ __forceinline__ uint32_t smem_u32(const void* p) {
    uint32_t a;
    asm("{ .reg .u64 t; cvta.to.shared.u64 t, %1; cvt.u32.u64 %0, t; }" : "=r"(a) : "l"(p));
    return a;
}

#define LDSM4(r0, r1, r2, r3, a) \
    asm volatile("ldmatrix.sync.aligned.m8n8.x4.shared.b16 {%0,%1,%2,%3}, [%4];" \
                 : "=r"(r0), "=r"(r1), "=r"(r2), "=r"(r3) : "r"(a))
#define MMA16816H(c, a0, a1, a2, a3, b0, b1) \
    asm volatile("mma.sync.aligned.m16n8k16.row.col.f32.f16.f16.f32 " \
                 "{%0,%1,%2,%3},{%4,%5,%6,%7},{%8,%9},{%0,%1,%2,%3};" \
                 : "+f"((c)[0]), "+f"((c)[1]), "+f"((c)[2]), "+f"((c)[3]) \
                 : "r"(a0), "r"(a1), "r"(a2), "r"(a3), "r"(b0), "r"(b1))

// ================= weight prep =================
__global__ void k_prepw1(const float* __restrict__ W1) {
    int idx = blockIdx.x * blockDim.x + threadIdx.x;
    if (idx >= 32768) return;
    int k = idx >> 8, n = idx & 255;
    float v = __ldg(&W1[idx]);
    int ct = n >> 7, nl = n & 127;
    g_w1h[ct * 16384 + nl * 128 + k] = __float2half_rn(v);
}
__global__ void k_prepw2(const float* __restrict__ W2) {
    int idx = blockIdx.x * blockDim.x + threadIdx.x;
    if (idx >= 8192) return;
    int k = idx >> 5, n = idx & 31;
    float v = __ldg(&W2[idx]);
    __half hi = __float2half_rn(v);
    __half lo = __float2half_rn(v - __half2float(hi));
    g_w2hi[n * 256 + k] = hi;
    g_w2lo[n * 256 + k] = lo;
}

// ================= CSR build =================
__global__ void k_zero() {
    int i = blockIdx.x * blockDim.x + threadIdx.x;
    if (i < NN) g_cnt[i] = 0;
}
__global__ void k_hist(const int* __restrict__ ei) {
    int e = blockIdx.x * blockDim.x + threadIdx.x;
    if (e < EE) atomicAdd(&g_cnt[ei[EE + e]], 1);
}
__global__ void __launch_bounds__(1024) k_scan1() {
    __shared__ int ws[32];
    int tid = threadIdx.x, lane = tid & 31, wid = tid >> 5;
    int i = blockIdx.x * 1024 + tid;
    int v = (i < NN) ? g_cnt[i] : 0;
    int x = v;
    #pragma unroll
    for (int o = 1; o < 32; o <<= 1) {
        int y = __shfl_up_sync(0xffffffffu, x, o);
        if (lane >= o) x += y;
    }
    if (lane == 31) ws[wid] = x;
    __syncthreads();
    if (wid == 0) {
        int s = ws[lane];
        #pragma unroll
        for (int o = 1; o < 32; o <<= 1) {
            int y = __shfl_up_sync(0xffffffffu, s, o);
            if (lane >= o) s += y;
        }
        ws[lane] = s;
    }
    __syncthreads();
    int incl = x + (wid ? ws[wid - 1] : 0);
    if (i < NN) g_rowptr[i] = incl - v;
    if (tid == 1023) g_bsum[blockIdx.x] = incl;
}
__global__ void k_scan2(int nblk) {
    __shared__ int ws[4];
    int tid = threadIdx.x, lane = tid & 31, wid = tid >> 5;
    int v = (tid < nblk) ? g_bsum[tid] : 0;
    int x = v;
    #pragma unroll
    for (int o = 1; o < 32; o <<= 1) {
        int y = __shfl_up_sync(0xffffffffu, x, o);
        if (lane >= o) x += y;
    }
    if (lane == 31) ws[wid] = x;
    __syncthreads();
    int pre = 0;
    for (int w = 0; w < wid; w++) pre += ws[w];
    int incl = x + pre;
    if (tid < nblk) g_boff[tid] = incl - v;
    if (tid == nblk - 1) g_rowptr[NN] = incl;
}
__global__ void __launch_bounds__(1024) k_scan3() {
    int i = blockIdx.x * 1024 + threadIdx.x;
    if (i < NN) {
        int r = g_rowptr[i] + g_boff[blockIdx.x];
        g_rowptr[i] = r;
        g_cursor[i] = r;
    }
}
__global__ void k_scatter(const int* __restrict__ ei) {
    int e = blockIdx.x * blockDim.x + threadIdx.x;
    if (e < EE) {
        int s = ei[e];
        int d = ei[EE + e];
        int pos = atomicAdd(&g_cursor[d], 1);
        g_col[pos] = s;
    }
}

// ======== GEMM1: fp16 2-term (A split hi+lo, B single), 3 CTAs/SM + fused att1 ========
// (R14-proven configuration)
#define SKEW 136
#define SA_HI 0
#define SA_LO 17408
#define SB_H  34816
#define SM_G1 69632

__global__ void __launch_bounds__(256, 3) k_gemm1_mma(const float* __restrict__ x0,
                                                      const float* __restrict__ attS,
                                                      const float* __restrict__ attD) {
    extern __shared__ __align__(128) char smem[];
    __half* sAhi = (__half*)(smem + SA_HI);
    __half* sAlo = (__half*)(smem + SA_LO);
    __half* sB   = (__half*)(smem + SB_H);
    uint32_t sb = smem_u32(smem);

    int tid = threadIdx.x;
    int rowBase = blockIdx.x * 64;

    #pragma unroll 4
    for (int i = 0; i < 32; i++) {
        int idx = i * 256 + tid;
        int r = idx >> 7, c = idx & 127;
        int grow = rowBase + r;
        float v = (grow < NN) ? __ldg(&x0[(size_t)grow * 128 + c]) : 0.f;
        __half hi = __float2half_rn(v);
        __half lo = __float2half_rn(v - __half2float(hi));
        sAhi[r * SKEW + c] = hi;
        sAlo[r * SKEW + c] = lo;
    }

    int wid = tid >> 5, lane = tid & 31;
    int warpM = wid >> 2, warpN = wid & 3;
    int aRow = warpM * 32 + (lane & 15);
    int aColHalf = (lane >> 4) * 8;
    int bRowX4 = ((lane >> 4) * 8) + (lane & 7);
    int bColHalf = ((lane >> 3) & 1) * 8;
    int rq = lane >> 2, cq = (lane & 3) * 2;

    #pragma unroll 1
    for (int ct = 0; ct < 2; ct++) {
        __syncthreads();
        {
            const uint4* src = (const uint4*)(g_w1h + ct * 16384);
            #pragma unroll
            for (int i = 0; i < 8; i++) {
                int q = i * 256 + tid;
                int nl = q >> 4, k8 = (q & 15) * 8;
                *(uint4*)&sB[nl * SKEW + k8] = src[q];
            }
        }
        __syncthreads();

        float acc[2][4][4];
        #pragma unroll
        for (int mt = 0; mt < 2; mt++)
            #pragma unroll
            for (int nt = 0; nt < 4; nt++)
                #pragma unroll
                for (int q = 0; q < 4; q++) acc[mt][nt][q] = 0.f;

        #pragma unroll 1
        for (int ks = 0; ks < 8; ks++) {
            uint32_t ah[2][4], al[2][4], b[4][2];
            #pragma unroll
            for (int mt = 0; mt < 2; mt++) {
                uint32_t off = (uint32_t)(((aRow + mt * 16) * SKEW) + ks * 16 + aColHalf) * 2;
                LDSM4(ah[mt][0], ah[mt][1], ah[mt][2], ah[mt][3], sb + SA_HI + off);
                LDSM4(al[mt][0], al[mt][1], al[mt][2], al[mt][3], sb + SA_LO + off);
            }
            #pragma unroll
            for (int p = 0; p < 2; p++) {
                uint32_t off = (uint32_t)(((warpN * 32 + p * 16 + bRowX4) * SKEW) + ks * 16 + bColHalf) * 2;
                LDSM4(b[2 * p][0], b[2 * p][1], b[2 * p + 1][0], b[2 * p + 1][1], sb + SB_H + off);
            }
            #pragma unroll
            for (int mt = 0; mt < 2; mt++)
                #pragma unroll
                for (int nt = 0; nt < 4; nt++) {
                    MMA16816H(acc[mt][nt], ah[mt][0], ah[mt][1], ah[mt][2], ah[mt][3],
                              b[nt][0], b[nt][1]);
                    MMA16816H(acc[mt][nt], al[mt][0], al[mt][1], al[mt][2], al[mt][3],
                              b[nt][0], b[nt][1]);
                }
        }

        int h = ct * 4 + warpN;
        float aS[8], aD[8];
        #pragma unroll
        for (int nt = 0; nt < 4; nt++) {
            aS[nt * 2 + 0] = __ldg(&attS[h * 32 + nt * 8 + cq]);
            aS[nt * 2 + 1] = __ldg(&attS[h * 32 + nt * 8 + cq + 1]);
            aD[nt * 2 + 0] = __ldg(&attD[h * 32 + nt * 8 + cq]);
            aD[nt * 2 + 1] = __ldg(&attD[h * 32 + nt * 8 + cq + 1]);
        }
        #pragma unroll
        for (int mt = 0; mt < 2; mt++) {
            int r0 = rowBase + warpM * 32 + mt * 16 + rq;
            int r1 = r0 + 8;
            float ps0 = 0.f, pd0 = 0.f, ps1 = 0.f, pd1 = 0.f;
            #pragma unroll
            for (int nt = 0; nt < 4; nt++) {
                ps0 += acc[mt][nt][0] * aS[nt * 2] + acc[mt][nt][1] * aS[nt * 2 + 1];
                pd0 += acc[mt][nt][0] * aD[nt * 2] + acc[mt][nt][1] * aD[nt * 2 + 1];
                ps1 += acc[mt][nt][2] * aS[nt * 2] + acc[mt][nt][3] * aS[nt * 2 + 1];
                pd1 += acc[mt][nt][2] * aD[nt * 2] + acc[mt][nt][3] * aD[nt * 2 + 1];
                int cc = ct * 128 + warpN * 32 + nt * 8 + cq;
                if (r0 < NN)
                    *(__half2*)&g_h1h[(size_t)r0 * 256 + cc] =
                        __floats2half2_rn(acc[mt][nt][0], acc[mt][nt][1]);
                if (r1 < NN)
                    *(__half2*)&g_h1h[(size_t)r1 * 256 + cc] =
                        __floats2half2_rn(acc[mt][nt][2], acc[mt][nt][3]);
            }
            #pragma unroll
            for (int o = 1; o <= 2; o <<= 1) {
                ps0 += __shfl_xor_sync(0xffffffffu, ps0, o);
                pd0 += __shfl_xor_sync(0xffffffffu, pd0, o);
                ps1 += __shfl_xor_sync(0xffffffffu, ps1, o);
                pd1 += __shfl_xor_sync(0xffffffffu, pd1, o);
            }
            if ((lane & 3) == 0) {
                if (r0 < NN) { g_as1[r0 * 8 + h] = ps0; g_ad1[r0 * 8 + h] = pd0; }
                if (r1 < NN) { g_as1[r1 * 8 + h] = ps1; g_ad1[r1 * 8 + h] = pd1; }
            }
        }
    }
}

// ============ GAT1: grid-stride node loop; lane owns 8 ch of ONE head; 16B loads ============
#define GAT1_BLOCKS 1536
__global__ void __launch_bounds__(256) k_gat1(const float* __restrict__ b1) {
    int warpG = (blockIdx.x * blockDim.x + threadIdx.x) >> 5;
    int nWarps = GAT1_BLOCKS * 8;
    int lane = threadIdx.x & 31;
    int hh = lane >> 2;
    int c8 = (lane & 3) * 8;
    int coff = hh * 32 + c8;

    float4 bb0 = __ldg((const float4*)&b1[coff]);
    float4 bb1 = __ldg((const float4*)&b1[coff + 4]);
    float bv[8] = {bb0.x, bb0.y, bb0.z, bb0.w, bb1.x, bb1.y, bb1.z, bb1.w};

    for (int n = warpG; n < NN; n += nWarps) {
        float ad = __ldg(&g_ad1[n * 8 + hh]);

        float den = __expf(leaky(__ldg(&g_as1[n * 8 + hh]) + ad));   // self loop
        float acc[8];
        {
            uint4 rh = *(const uint4*)&g_h1h[(size_t)n * 256 + coff];
            const __half2* hp = (const __half2*)&rh;
            #pragma unroll
            for (int j = 0; j < 4; j++) {
                float2 f = __half22float2(hp[j]);
                acc[2 * j]     = den * f.x;
                acc[2 * j + 1] = den * f.y;
            }
        }

        int e0 = g_rowptr[n], e1 = g_rowptr[n + 1];
        #pragma unroll 4
        for (int p = e0; p < e1; p++) {
            int s = __ldg(&g_col[p]);
            float w = __expf(leaky(__ldg(&g_as1[s * 8 + hh]) + ad));
            den += w;
            uint4 rh = *(const uint4*)&g_h1h[(size_t)s * 256 + coff];
            const __half2* hp = (const __half2*)&rh;
            #pragma unroll
            for (int j = 0; j < 4; j++) {
                float2 f = __half22float2(hp[j]);
                acc[2 * j]     += w * f.x;
                acc[2 * j + 1] += w * f.y;
            }
        }

        float inv = 1.f / fmaxf(den, 1e-16f);
        uint4 outp;
        __half2* op = (__half2*)&outp;
        #pragma unroll
        for (int j = 0; j < 4; j++) {
            float r0 = fmaxf(acc[2 * j]     * inv + bv[2 * j],     0.f);
            float r1 = fmaxf(acc[2 * j + 1] * inv + bv[2 * j + 1], 0.f);
            op[j] = __floats2half2_rn(r0, r1);
        }
        __stcs((uint4*)&g_x2h[(size_t)n * 256 + coff], outp);
    }
}

// ======== GEMM2 via fp16 mma: h2 = x2 @ W2 (K=256 -> 32) + fused att2 dots ========
#define SKEW2 264
#define G2_SA  0
#define G2_SBH 67584
#define G2_SBL 84480
#define SM_G2  101376

__global__ void __launch_bounds__(256, 2) k_gemm2_mma(const float* __restrict__ attS2,
                                                      const float* __restrict__ attD2) {
    extern __shared__ __align__(128) char smem[];
    __half* sA  = (__half*)(smem + G2_SA);
    __half* sBh = (__half*)(smem + G2_SBH);
    __half* sBl = (__half*)(smem + G2_SBL);
    uint32_t sb = smem_u32(smem);

    int tid = threadIdx.x;
    int rowBase = blockIdx.x * 128;

    #pragma unroll 4
    for (int i = 0; i < 16; i++) {
        int q = i * 256 + tid;
        int r = q >> 5, c8 = (q & 31) * 8;
        int grow = rowBase + r;
        uint4 v = (grow < NN) ? *(const uint4*)&g_x2h[(size_t)grow * 256 + c8]
                              : make_uint4(0, 0, 0, 0);
        *(uint4*)&sA[r * SKEW2 + c8] = v;
    }
    #pragma unroll
    for (int i = 0; i < 4; i++) {
        int q = i * 256 + tid;
        int nl = q >> 5, k8 = (q & 31) * 8;
        *(uint4*)&sBh[nl * SKEW2 + k8] = *(const uint4*)&g_w2hi[nl * 256 + k8];
        *(uint4*)&sBl[nl * SKEW2 + k8] = *(const uint4*)&g_w2lo[nl * 256 + k8];
    }
    __syncthreads();

    int wid = tid >> 5, lane = tid & 31;
    int aRow = wid * 16 + (lane & 15);
    int aColHalf = (lane >> 4) * 8;
    int bRowX4 = ((lane >> 4) * 8) + (lane & 7);
    int bColHalf = ((lane >> 3) & 1) * 8;
    int rq = lane >> 2, cq = (lane & 3) * 2;

    float acc[4][4];
    #pragma unroll
    for (int nt = 0; nt < 4; nt++)
        #pragma unroll
        for (int q = 0; q < 4; q++) acc[nt][q] = 0.f;

    #pragma unroll 2
    for (int ks = 0; ks < 16; ks++) {
        uint32_t a[4], bh[4][2], bl[4][2];
        LDSM4(a[0], a[1], a[2], a[3],
              sb + G2_SA + (uint32_t)(aRow * SKEW2 + ks * 16 + aColHalf) * 2);
        #pragma unroll
        for (int p = 0; p < 2; p++) {
            uint32_t off = (uint32_t)((p * 16 + bRowX4) * SKEW2 + ks * 16 + bColHalf) * 2;
            LDSM4(bh[2 * p][0], bh[2 * p][1], bh[2 * p + 1][0], bh[2 * p + 1][1], sb + G2_SBH + off);
            LDSM4(bl[2 * p][0], bl[2 * p][1], bl[2 * p + 1][0], bl[2 * p + 1][1], sb + G2_SBL + off);
        }
        #pragma unroll
        for (int nt = 0; nt < 4; nt++) {
            MMA16816H(acc[nt], a[0], a[1], a[2], a[3], bh[nt][0], bh[nt][1]);
            MMA16816H(acc[nt], a[0], a[1], a[2], a[3], bl[nt][0], bl[nt][1]);
        }
    }

    float aS[8], aD[8];
    #pragma unroll
    for (int nt = 0; nt < 4; nt++) {
        aS[nt * 2 + 0] = __ldg(&attS2[nt * 8 + cq]);
        aS[nt * 2 + 1] = __ldg(&attS2[nt * 8 + cq + 1]);
        aD[nt * 2 + 0] = __ldg(&attD2[nt * 8 + cq]);
        aD[nt * 2 + 1] = __ldg(&attD2[nt * 8 + cq + 1]);
    }
    int r0 = rowBase + wid * 16 + rq;
    int r1 = r0 + 8;
    float ps0 = 0.f, pd0 = 0.f, ps1 = 0.f, pd1 = 0.f;
    #pragma unroll
    for (int nt = 0; nt < 4; nt++) {
        ps0 += acc[nt][0] * aS[nt * 2] + acc[nt][1] * aS[nt * 2 + 1];
        pd0 += acc[nt][0] * aD[nt * 2] + acc[nt][1] * aD[nt * 2 + 1];
        ps1 += acc[nt][2] * aS[nt * 2] + acc[nt][3] * aS[nt * 2 + 1];
        pd1 += acc[nt][2] * aD[nt * 2] + acc[nt][3] * aD[nt * 2 + 1];
        int cc = nt * 8 + cq;
        if (r0 < NN)
            *(__half2*)&g_h2h[r0 * 32 + cc] = __floats2half2_rn(acc[nt][0], acc[nt][1]);
        if (r1 < NN)
            *(__half2*)&g_h2h[r1 * 32 + cc] = __floats2half2_rn(acc[nt][2], acc[nt][3]);
    }
    #pragma unroll
    for (int o = 1; o <= 2; o <<= 1) {
        ps0 += __shfl_xor_sync(0xffffffffu, ps0, o);
        pd0 += __shfl_xor_sync(0xffffffffu, pd0, o);
        ps1 += __shfl_xor_sync(0xffffffffu, ps1, o);
        pd1 += __shfl_xor_sync(0xffffffffu, pd1, o);
    }
    if ((lane & 3) == 0) {
        if (r0 < NN) { g_as2[r0] = ps0; g_ad2[r0] = pd0; }
        if (r1 < NN) { g_as2[r1] = ps1; g_ad2[r1] = pd1; }
    }
}

// ============ GAT2 (4-edge groups, fp16 8B loads) + fused final linear ============
__global__ void __launch_bounds__(256) k_gat2(const float* __restrict__ b2,
                                              const float* __restrict__ linW,
                                              const float* __restrict__ linb,
                                              float* __restrict__ out) {
    __shared__ float lw[32 * 40];
    __shared__ float rows[8][32];
    int tid = threadIdx.x;
    for (int i = tid; i < 32 * 40; i += 256) lw[i] = linW[i];

    int wl = tid >> 5, lane = tid & 31;
    int n = blockIdx.x * 8 + wl;
    int grp = lane >> 3, c4 = (lane & 7) * 4;

    float adst = g_ad2[n];
    float asn  = g_as2[n];
    float den; float4 acc;
    {
        float ws = __expf(leaky(asn + adst));
        if (grp == 0) {
            uint2 rh = *(const uint2*)&g_h2h[n * 32 + c4];
            float2 h01 = __half22float2(*(__half2*)&rh.x);
            float2 h23 = __half22float2(*(__half2*)&rh.y);
            den = ws;
            acc = make_float4(ws * h01.x, ws * h01.y, ws * h23.x, ws * h23.y);
        } else {
            den = 0.f;
            acc = make_float4(0.f, 0.f, 0.f, 0.f);
        }
    }
    int e0 = g_rowptr[n], e1 = g_rowptr[n + 1];
    #pragma unroll 2
    for (int p0 = e0; p0 < e1; p0 += 4) {
        int p = p0 + grp;
        bool v = p < e1;
        int s = v ? __ldg(&g_col[p]) : n;
        float w = v ? __expf(leaky(__ldg(&g_as2[s]) + adst)) : 0.f;
        den += w;
        uint2 rh = *(const uint2*)&g_h2h[s * 32 + c4];
        float2 h01 = __half22float2(*(__half2*)&rh.x);
        float2 h23 = __half22float2(*(__half2*)&rh.y);
        acc.x += w * h01.x; acc.y += w * h01.y; acc.z += w * h23.x; acc.w += w * h23.y;
    }
    #pragma unroll
    for (int o = 8; o <= 16; o <<= 1) {
        acc.x += __shfl_xor_sync(0xffffffffu, acc.x, o);
        acc.y += __shfl_xor_sync(0xffffffffu, acc.y, o);
        acc.z += __shfl_xor_sync(0xffffffffu, acc.z, o);
        acc.w += __shfl_xor_sync(0xffffffffu, acc.w, o);
        den   += __shfl_xor_sync(0xffffffffu, den, o);
    }
    if (grp == 0) {
        float inv = 1.f / fmaxf(den, 1e-16f);
        float4 bb = __ldg((const float4*)&b2[c4]);
        rows[wl][c4 + 0] = acc.x * inv + bb.x;
        rows[wl][c4 + 1] = acc.y * inv + bb.y;
        rows[wl][c4 + 2] = acc.z * inv + bb.z;
        rows[wl][c4 + 3] = acc.w * inv + bb.w;
    }
    __syncthreads();
    int nb = blockIdx.x * 8;
    for (int t = tid; t < 320; t += 256) {
        int r = t / 40, o = t % 40;
        float s = __ldg(&linb[o]);
        #pragma unroll
        for (int k = 0; k < 32; k++) s += rows[r][k] * lw[k * 40 + o];
        out[(size_t)(nb + r) * 40 + o] = s;
    }
}

// ================= launch =================
extern "C" void kernel_launch(void* const* d_in, const int* in_sizes, int n_in,
                              void* d_out, int out_size) {
    const float* x0    = (const float*)d_in[0];
    const float* W1    = (const float*)d_in[1];
    const float* attS1 = (const float*)d_in[2];
    const float* attD1 = (const float*)d_in[3];
    const float* b1    = (const float*)d_in[4];
    const float* W2    = (const float*)d_in[5];
    const float* attS2 = (const float*)d_in[6];
    const float* attD2 = (const float*)d_in[7];
    const float* b2    = (const float*)d_in[8];
    const float* linW  = (const float*)d_in[9];
    const float* linb  = (const float*)d_in[10];
    const int*   ei    = (const int*)d_in[11];
    float* out = (float*)d_out;

    static cudaStream_t s_side = nullptr;
    static cudaEvent_t ev_fork = nullptr, ev_join = nullptr;
    if (!s_side) {
        cudaFuncSetAttribute(k_gemm1_mma, cudaFuncAttributeMaxDynamicSharedMemorySize, SM_G1);
        cudaFuncSetAttribute(k_gemm2_mma, cudaFuncAttributeMaxDynamicSharedMemorySize, SM_G2);
        cudaStreamCreateWithFlags(&s_side, cudaStreamNonBlocking);
        cudaEventCreateWithFlags(&ev_fork, cudaEventDisableTiming);
        cudaEventCreateWithFlags(&ev_join, cudaEventDisableTiming);
    }

    const int NBLK = (NN + 1023) / 1024;   // 98

    cudaEventRecord(ev_fork, 0);
    cudaStreamWaitEvent(s_side, ev_fork, 0);
    k_prepw1<<<128, 256>>>(W1);                                  // 1 (main)
    k_zero<<<(NN + 255) / 256, 256, 0, s_side>>>();              // 2 (side)
    k_hist<<<(EE + 255) / 256, 256, 0, s_side>>>(ei);            // 3 (side)
    k_gemm1_mma<<<(NN + 63) / 64, 256, SM_G1>>>(x0, attS1, attD1); // 4 (main)
    k_prepw2<<<32, 256, 0, s_side>>>(W2);                        // 5 (side)
    k_scan1<<<NBLK, 1024, 0, s_side>>>();                        // 6
    k_scan2<<<1, 128, 0, s_side>>>(NBLK);                        // 7
    k_scan3<<<NBLK, 1024, 0, s_side>>>();                        // 8
    k_scatter<<<(EE + 255) / 256, 256, 0, s_side>>>(ei);         // 9
    cudaEventRecord(ev_join, s_side);

    cudaStreamWaitEvent(0, ev_join, 0);
    k_gat1<<<GAT1_BLOCKS, 256>>>(b1);
    k_gemm2_mma<<<(NN + 127) / 128, 256, SM_G2>>>(attS2, attD2);
    k_gat2<<<NN / 8, 256>>>(b2, linW, linb, out);
}

// round 17
// speedup vs baseline: 1.0796x; 1.0796x over previous
#include <cuda_runtime.h>
#include <cuda_bf16.h>
#include <cuda_fp16.h>
#include <cstdint>

#define NN   100000
#define EE   1000000
#define HID  32
#define NH1  8
#define OUTC 40
#define NEGS 0.2f

// ================= device scratch =================
__device__ __align__(16) __half g_h1h[(size_t)NN * 256];   // layer1 messages, fp16
__device__ __align__(16) __half g_x2h[(size_t)NN * 256];   // relu(layer1 out), fp16
__device__ __align__(16) float g_as1[NN * NH1];
__device__ __align__(16) float g_ad1[NN * NH1];
__device__ __align__(16) __half g_h2h[NN * HID];           // layer2 messages, fp16
__device__ __align__(16) float g_as2[NN];
__device__ __align__(16) float g_ad2[NN];
__device__ __align__(16) __half g_w1h[32768];              // W1 fp16, tile layout [ct][n][k]
__device__ __align__(16) __half g_w2hi[8192];              // W2 split fp16, [n][k] layout
__device__ __align__(16) __half g_w2lo[8192];
__device__ int g_cnt[NN];
__device__ int g_rowptr[NN + 1];
__device__ int g_cursor[NN];
__device__ int g_col[EE];
__device__ int g_bsum[128];
__device__ int g_boff[128];

__device__ __forceinline__ float leaky(float x) { return x > 0.f ? x : NEGS * x; }

__device__ __forceinline__ uint32_t smem_u32(const void* p) {
    uint32_t a;
    asm("{ .reg .u64 t; cvta.to.shared.u64 t, %1; cvt.u32.u64 %0, t; }" : "=r"(a) : "l"(p));
    return a;
}

#define LDSM4(r0, r1, r2, r3, a) \
    asm volatile("ldmatrix.sync.aligned.m8n8.x4.shared.b16 {%0,%1,%2,%3}, [%4];" \
                 : "=r"(r0), "=r"(r1), "=r"(r2), "=r"(r3) : "r"(a))
#define MMA16816H(c, a0, a1, a2, a3, b0, b1) \
    asm volatile("mma.sync.aligned.m16n8k16.row.col.f32.f16.f16.f32 " \
                 "{%0,%1,%2,%3},{%4,%5,%6,%7},{%8,%9},{%0,%1,%2,%3};" \
                 : "+f"((c)[0]), "+f"((c)[1]), "+f"((c)[2]), "+f"((c)[3]) \
                 : "r"(a0), "r"(a1), "r"(a2), "r"(a3), "r"(b0), "r"(b1))

// ================= weight prep =================
__global__ void k_prepw1(const float* __restrict__ W1) {
    int idx = blockIdx.x * blockDim.x + threadIdx.x;
    if (idx >= 32768) return;
    int k = idx >> 8, n = idx & 255;
    float v = __ldg(&W1[idx]);
    int ct = n >> 7, nl = n & 127;
    g_w1h[ct * 16384 + nl * 128 + k] = __float2half_rn(v);
}
__global__ void k_prepw2(const float* __restrict__ W2) {
    int idx = blockIdx.x * blockDim.x + threadIdx.x;
    if (idx >= 8192) return;
    int k = idx >> 5, n = idx & 31;
    float v = __ldg(&W2[idx]);
    __half hi = __float2half_rn(v);
    __half lo = __float2half_rn(v - __half2float(hi));
    g_w2hi[n * 256 + k] = hi;
    g_w2lo[n * 256 + k] = lo;
}

// ================= CSR build =================
__global__ void k_zero() {
    int i = blockIdx.x * blockDim.x + threadIdx.x;
    if (i < NN) g_cnt[i] = 0;
}
__global__ void k_hist(const int* __restrict__ ei) {
    int e = blockIdx.x * blockDim.x + threadIdx.x;
    if (e < EE) atomicAdd(&g_cnt[ei[EE + e]], 1);
}
__global__ void __launch_bounds__(1024) k_scan1() {
    __shared__ int ws[32];
    int tid = threadIdx.x, lane = tid & 31, wid = tid >> 5;
    int i = blockIdx.x * 1024 + tid;
    int v = (i < NN) ? g_cnt[i] : 0;
    int x = v;
    #pragma unroll
    for (int o = 1; o < 32; o <<= 1) {
        int y = __shfl_up_sync(0xffffffffu, x, o);
        if (lane >= o) x += y;
    }
    if (lane == 31) ws[wid] = x;
    __syncthreads();
    if (wid == 0) {
        int s = ws[lane];
        #pragma unroll
        for (int o = 1; o < 32; o <<= 1) {
            int y = __shfl_up_sync(0xffffffffu, s, o);
            if (lane >= o) s += y;
        }
        ws[lane] = s;
    }
    __syncthreads();
    int incl = x + (wid ? ws[wid - 1] : 0);
    if (i < NN) g_rowptr[i] = incl - v;
    if (tid == 1023) g_bsum[blockIdx.x] = incl;
}
__global__ void k_scan2(int nblk) {
    __shared__ int ws[4];
    int tid = threadIdx.x, lane = tid & 31, wid = tid >> 5;
    int v = (tid < nblk) ? g_bsum[tid] : 0;
    int x = v;
    #pragma unroll
    for (int o = 1; o < 32; o <<= 1) {
        int y = __shfl_up_sync(0xffffffffu, x, o);
        if (lane >= o) x += y;
    }
    if (lane == 31) ws[wid] = x;
    __syncthreads();
    int pre = 0;
    for (int w = 0; w < wid; w++) pre += ws[w];
    int incl = x + pre;
    if (tid < nblk) g_boff[tid] = incl - v;
    if (tid == nblk - 1) g_rowptr[NN] = incl;
}
__global__ void __launch_bounds__(1024) k_scan3() {
    int i = blockIdx.x * 1024 + threadIdx.x;
    if (i < NN) {
        int r = g_rowptr[i] + g_boff[blockIdx.x];
        g_rowptr[i] = r;
        g_cursor[i] = r;
    }
}
__global__ void k_scatter(const int* __restrict__ ei) {
    int e = blockIdx.x * blockDim.x + threadIdx.x;
    if (e < EE) {
        int s = ei[e];
        int d = ei[EE + e];
        int pos = atomicAdd(&g_cursor[d], 1);
        g_col[pos] = s;
    }
}

// ======== GEMM1: fp16 2-term (A split hi+lo, B single), 3 CTAs/SM + fused att1 ========
// (R14-proven configuration)
#define SKEW 136
#define SA_HI 0
#define SA_LO 17408
#define SB_H  34816
#define SM_G1 69632

__global__ void __launch_bounds__(256, 3) k_gemm1_mma(const float* __restrict__ x0,
                                                      const float* __restrict__ attS,
                                                      const float* __restrict__ attD) {
    extern __shared__ __align__(128) char smem[];
    __half* sAhi = (__half*)(smem + SA_HI);
    __half* sAlo = (__half*)(smem + SA_LO);
    __half* sB   = (__half*)(smem + SB_H);
    uint32_t sb = smem_u32(smem);

    int tid = threadIdx.x;
    int rowBase = blockIdx.x * 64;

    #pragma unroll 4
    for (int i = 0; i < 32; i++) {
        int idx = i * 256 + tid;
        int r = idx >> 7, c = idx & 127;
        int grow = rowBase + r;
        float v = (grow < NN) ? __ldg(&x0[(size_t)grow * 128 + c]) : 0.f;
        __half hi = __float2half_rn(v);
        __half lo = __float2half_rn(v - __half2float(hi));
        sAhi[r * SKEW + c] = hi;
        sAlo[r * SKEW + c] = lo;
    }

    int wid = tid >> 5, lane = tid & 31;
    int warpM = wid >> 2, warpN = wid & 3;
    int aRow = warpM * 32 + (lane & 15);
    int aColHalf = (lane >> 4) * 8;
    int bRowX4 = ((lane >> 4) * 8) + (lane & 7);
    int bColHalf = ((lane >> 3) & 1) * 8;
    int rq = lane >> 2, cq = (lane & 3) * 2;

    #pragma unroll 1
    for (int ct = 0; ct < 2; ct++) {
        __syncthreads();
        {
            const uint4* src = (const uint4*)(g_w1h + ct * 16384);
            #pragma unroll
            for (int i = 0; i < 8; i++) {
                int q = i * 256 + tid;
                int nl = q >> 4, k8 = (q & 15) * 8;
                *(uint4*)&sB[nl * SKEW + k8] = src[q];
            }
        }
        __syncthreads();

        float acc[2][4][4];
        #pragma unroll
        for (int mt = 0; mt < 2; mt++)
            #pragma unroll
            for (int nt = 0; nt < 4; nt++)
                #pragma unroll
                for (int q = 0; q < 4; q++) acc[mt][nt][q] = 0.f;

        #pragma unroll 1
        for (int ks = 0; ks < 8; ks++) {
            uint32_t ah[2][4], al[2][4], b[4][2];
            #pragma unroll
            for (int mt = 0; mt < 2; mt++) {
                uint32_t off = (uint32_t)(((aRow + mt * 16) * SKEW) + ks * 16 + aColHalf) * 2;
                LDSM4(ah[mt][0], ah[mt][1], ah[mt][2], ah[mt][3], sb + SA_HI + off);
                LDSM4(al[mt][0], al[mt][1], al[mt][2], al[mt][3], sb + SA_LO + off);
            }
            #pragma unroll
            for (int p = 0; p < 2; p++) {
                uint32_t off = (uint32_t)(((warpN * 32 + p * 16 + bRowX4) * SKEW) + ks * 16 + bColHalf) * 2;
                LDSM4(b[2 * p][0], b[2 * p][1], b[2 * p + 1][0], b[2 * p + 1][1], sb + SB_H + off);
            }
            #pragma unroll
            for (int mt = 0; mt < 2; mt++)
                #pragma unroll
                for (int nt = 0; nt < 4; nt++) {
                    MMA16816H(acc[mt][nt], ah[mt][0], ah[mt][1], ah[mt][2], ah[mt][3],
                              b[nt][0], b[nt][1]);
                    MMA16816H(acc[mt][nt], al[mt][0], al[mt][1], al[mt][2], al[mt][3],
                              b[nt][0], b[nt][1]);
                }
        }

        int h = ct * 4 + warpN;
        float aS[8], aD[8];
        #pragma unroll
        for (int nt = 0; nt < 4; nt++) {
            aS[nt * 2 + 0] = __ldg(&attS[h * 32 + nt * 8 + cq]);
            aS[nt * 2 + 1] = __ldg(&attS[h * 32 + nt * 8 + cq + 1]);
            aD[nt * 2 + 0] = __ldg(&attD[h * 32 + nt * 8 + cq]);
            aD[nt * 2 + 1] = __ldg(&attD[h * 32 + nt * 8 + cq + 1]);
        }
        #pragma unroll
        for (int mt = 0; mt < 2; mt++) {
            int r0 = rowBase + warpM * 32 + mt * 16 + rq;
            int r1 = r0 + 8;
            float ps0 = 0.f, pd0 = 0.f, ps1 = 0.f, pd1 = 0.f;
            #pragma unroll
            for (int nt = 0; nt < 4; nt++) {
                ps0 += acc[mt][nt][0] * aS[nt * 2] + acc[mt][nt][1] * aS[nt * 2 + 1];
                pd0 += acc[mt][nt][0] * aD[nt * 2] + acc[mt][nt][1] * aD[nt * 2 + 1];
                ps1 += acc[mt][nt][2] * aS[nt * 2] + acc[mt][nt][3] * aS[nt * 2 + 1];
                pd1 += acc[mt][nt][2] * aD[nt * 2] + acc[mt][nt][3] * aD[nt * 2 + 1];
                int cc = ct * 128 + warpN * 32 + nt * 8 + cq;
                if (r0 < NN)
                    *(__half2*)&g_h1h[(size_t)r0 * 256 + cc] =
                        __floats2half2_rn(acc[mt][nt][0], acc[mt][nt][1]);
                if (r1 < NN)
                    *(__half2*)&g_h1h[(size_t)r1 * 256 + cc] =
                        __floats2half2_rn(acc[mt][nt][2], acc[mt][nt][3]);
            }
            #pragma unroll
            for (int o = 1; o <= 2; o <<= 1) {
                ps0 += __shfl_xor_sync(0xffffffffu, ps0, o);
                pd0 += __shfl_xor_sync(0xffffffffu, pd0, o);
                ps1 += __shfl_xor_sync(0xffffffffu, ps1, o);
                pd1 += __shfl_xor_sync(0xffffffffu, pd1, o);
            }
            if ((lane & 3) == 0) {
                if (r0 < NN) { g_as1[r0 * 8 + h] = ps0; g_ad1[r0 * 8 + h] = pd0; }
                if (r1 < NN) { g_as1[r1 * 8 + h] = ps1; g_ad1[r1 * 8 + h] = pd1; }
            }
        }
    }
}

// ============ GAT1 (R14-proven): warp per node; lane owns 8 ch of ONE head; 16B loads ============
__global__ void __launch_bounds__(256) k_gat1(const float* __restrict__ b1) {
    int n = (blockIdx.x * blockDim.x + threadIdx.x) >> 5;
    int lane = threadIdx.x & 31;
    if (n >= NN) return;
    int hh = lane >> 2;
    int c8 = (lane & 3) * 8;
    int coff = hh * 32 + c8;

    float ad = __ldg(&g_ad1[n * 8 + hh]);

    float den = __expf(leaky(__ldg(&g_as1[n * 8 + hh]) + ad));   // self loop
    float acc[8];
    {
        uint4 rh = *(const uint4*)&g_h1h[(size_t)n * 256 + coff];
        const __half2* hp = (const __half2*)&rh;
        #pragma unroll
        for (int j = 0; j < 4; j++) {
            float2 f = __half22float2(hp[j]);
            acc[2 * j]     = den * f.x;
            acc[2 * j + 1] = den * f.y;
        }
    }

    int e0 = g_rowptr[n], e1 = g_rowptr[n + 1];
    #pragma unroll 4
    for (int p = e0; p < e1; p++) {
        int s = __ldg(&g_col[p]);
        float w = __expf(leaky(__ldg(&g_as1[s * 8 + hh]) + ad));
        den += w;
        uint4 rh = *(const uint4*)&g_h1h[(size_t)s * 256 + coff];
        const __half2* hp = (const __half2*)&rh;
        #pragma unroll
        for (int j = 0; j < 4; j++) {
            float2 f = __half22float2(hp[j]);
            acc[2 * j]     += w * f.x;
            acc[2 * j + 1] += w * f.y;
        }
    }

    float inv = 1.f / fmaxf(den, 1e-16f);
    float4 bb0 = __ldg((const float4*)&b1[coff]);
    float4 bb1 = __ldg((const float4*)&b1[coff + 4]);
    float bv[8] = {bb0.x, bb0.y, bb0.z, bb0.w, bb1.x, bb1.y, bb1.z, bb1.w};
    uint4 outp;
    __half2* op = (__half2*)&outp;
    #pragma unroll
    for (int j = 0; j < 4; j++) {
        float r0 = fmaxf(acc[2 * j]     * inv + bv[2 * j],     0.f);
        float r1 = fmaxf(acc[2 * j + 1] * inv + bv[2 * j + 1], 0.f);
        op[j] = __floats2half2_rn(r0, r1);
    }
    __stcs((uint4*)&g_x2h[(size_t)n * 256 + coff], outp);
}

// ======== GEMM2 via fp16 mma: h2 = x2 @ W2 (K=256 -> 32) + fused att2 dots ========
#define SKEW2 264
#define G2_SA  0
#define G2_SBH 67584
#define G2_SBL 84480
#define SM_G2  101376

__global__ void __launch_bounds__(256, 2) k_gemm2_mma(const float* __restrict__ attS2,
                                                      const float* __restrict__ attD2) {
    extern __shared__ __align__(128) char smem[];
    __half* sA  = (__half*)(smem + G2_SA);
    __half* sBh = (__half*)(smem + G2_SBH);
    __half* sBl = (__half*)(smem + G2_SBL);
    uint32_t sb = smem_u32(smem);

    int tid = threadIdx.x;
    int rowBase = blockIdx.x * 128;

    #pragma unroll 4
    for (int i = 0; i < 16; i++) {
        int q = i * 256 + tid;
        int r = q >> 5, c8 = (q & 31) * 8;
        int grow = rowBase + r;
        uint4 v = (grow < NN) ? __ldcs((const uint4*)&g_x2h[(size_t)grow * 256 + c8])
                              : make_uint4(0, 0, 0, 0);
        *(uint4*)&sA[r * SKEW2 + c8] = v;
    }
    #pragma unroll
    for (int i = 0; i < 4; i++) {
        int q = i * 256 + tid;
        int nl = q >> 5, k8 = (q & 31) * 8;
        *(uint4*)&sBh[nl * SKEW2 + k8] = *(const uint4*)&g_w2hi[nl * 256 + k8];
        *(uint4*)&sBl[nl * SKEW2 + k8] = *(const uint4*)&g_w2lo[nl * 256 + k8];
    }
    __syncthreads();

    int wid = tid >> 5, lane = tid & 31;
    int aRow = wid * 16 + (lane & 15);
    int aColHalf = (lane >> 4) * 8;
    int bRowX4 = ((lane >> 4) * 8) + (lane & 7);
    int bColHalf = ((lane >> 3) & 1) * 8;
    int rq = lane >> 2, cq = (lane & 3) * 2;

    float acc[4][4];
    #pragma unroll
    for (int nt = 0; nt < 4; nt++)
        #pragma unroll
        for (int q = 0; q < 4; q++) acc[nt][q] = 0.f;

    #pragma unroll 2
    for (int ks = 0; ks < 16; ks++) {
        uint32_t a[4], bh[4][2], bl[4][2];
        LDSM4(a[0], a[1], a[2], a[3],
              sb + G2_SA + (uint32_t)(aRow * SKEW2 + ks * 16 + aColHalf) * 2);
        #pragma unroll
        for (int p = 0; p < 2; p++) {
            uint32_t off = (uint32_t)((p * 16 + bRowX4) * SKEW2 + ks * 16 + bColHalf) * 2;
            LDSM4(bh[2 * p][0], bh[2 * p][1], bh[2 * p + 1][0], bh[2 * p + 1][1], sb + G2_SBH + off);
            LDSM4(bl[2 * p][0], bl[2 * p][1], bl[2 * p + 1][0], bl[2 * p + 1][1], sb + G2_SBL + off);
        }
        #pragma unroll
        for (int nt = 0; nt < 4; nt++) {
            MMA16816H(acc[nt], a[0], a[1], a[2], a[3], bh[nt][0], bh[nt][1]);
            MMA16816H(acc[nt], a[0], a[1], a[2], a[3], bl[nt][0], bl[nt][1]);
        }
    }

    float aS[8], aD[8];
    #pragma unroll
    for (int nt = 0; nt < 4; nt++) {
        aS[nt * 2 + 0] = __ldg(&attS2[nt * 8 + cq]);
        aS[nt * 2 + 1] = __ldg(&attS2[nt * 8 + cq + 1]);
        aD[nt * 2 + 0] = __ldg(&attD2[nt * 8 + cq]);
        aD[nt * 2 + 1] = __ldg(&attD2[nt * 8 + cq + 1]);
    }
    int r0 = rowBase + wid * 16 + rq;
    int r1 = r0 + 8;
    float ps0 = 0.f, pd0 = 0.f, ps1 = 0.f, pd1 = 0.f;
    #pragma unroll
    for (int nt = 0; nt < 4; nt++) {
        ps0 += acc[nt][0] * aS[nt * 2] + acc[nt][1] * aS[nt * 2 + 1];
        pd0 += acc[nt][0] * aD[nt * 2] + acc[nt][1] * aD[nt * 2 + 1];
        ps1 += acc[nt][2] * aS[nt * 2] + acc[nt][3] * aS[nt * 2 + 1];
        pd1 += acc[nt][2] * aD[nt * 2] + acc[nt][3] * aD[nt * 2 + 1];
        int cc = nt * 8 + cq;
        if (r0 < NN)
            *(__half2*)&g_h2h[r0 * 32 + cc] = __floats2half2_rn(acc[nt][0], acc[nt][1]);
        if (r1 < NN)
            *(__half2*)&g_h2h[r1 * 32 + cc] = __floats2half2_rn(acc[nt][2], acc[nt][3]);
    }
    #pragma unroll
    for (int o = 1; o <= 2; o <<= 1) {
        ps0 += __shfl_xor_sync(0xffffffffu, ps0, o);
        pd0 += __shfl_xor_sync(0xffffffffu, pd0, o);
        ps1 += __shfl_xor_sync(0xffffffffu, ps1, o);
        pd1 += __shfl_xor_sync(0xffffffffu, pd1, o);
    }
    if ((lane & 3) == 0) {
        if (r0 < NN) { g_as2[r0] = ps0; g_ad2[r0] = pd0; }
        if (r1 < NN) { g_as2[r1] = ps1; g_ad2[r1] = pd1; }
    }
}

// ============ GAT2 (4-edge groups, fp16 8B loads) + fused final linear ============
__global__ void __launch_bounds__(256) k_gat2(const float* __restrict__ b2,
                                              const float* __restrict__ linW,
                                              const float* __restrict__ linb,
                                              float* __restrict__ out) {
    __shared__ float lw[32 * 40];
    __shared__ float rows[8][32];
    int tid = threadIdx.x;
    for (int i = tid; i < 32 * 40; i += 256) lw[i] = linW[i];

    int wl = tid >> 5, lane = tid & 31;
    int n = blockIdx.x * 8 + wl;
    int grp = lane >> 3, c4 = (lane & 7) * 4;

    float adst = g_ad2[n];
    float asn  = g_as2[n];
    float den; float4 acc;
    {
        float ws = __expf(leaky(asn + adst));
        if (grp == 0) {
            uint2 rh = *(const uint2*)&g_h2h[n * 32 + c4];
            float2 h01 = __half22float2(*(__half2*)&rh.x);
            float2 h23 = __half22float2(*(__half2*)&rh.y);
            den = ws;
            acc = make_float4(ws * h01.x, ws * h01.y, ws * h23.x, ws * h23.y);
        } else {
            den = 0.f;
            acc = make_float4(0.f, 0.f, 0.f, 0.f);
        }
    }
    int e0 = g_rowptr[n], e1 = g_rowptr[n + 1];
    #pragma unroll 2
    for (int p0 = e0; p0 < e1; p0 += 4) {
        int p = p0 + grp;
        bool v = p < e1;
        int s = v ? __ldg(&g_col[p]) : n;
        float w = v ? __expf(leaky(__ldg(&g_as2[s]) + adst)) : 0.f;
        den += w;
        uint2 rh = *(const uint2*)&g_h2h[s * 32 + c4];
        float2 h01 = __half22float2(*(__half2*)&rh.x);
        float2 h23 = __half22float2(*(__half2*)&rh.y);
        acc.x += w * h01.x; acc.y += w * h01.y; acc.z += w * h23.x; acc.w += w * h23.y;
    }
    #pragma unroll
    for (int o = 8; o <= 16; o <<= 1) {
        acc.x += __shfl_xor_sync(0xffffffffu, acc.x, o);
        acc.y += __shfl_xor_sync(0xffffffffu, acc.y, o);
        acc.z += __shfl_xor_sync(0xffffffffu, acc.z, o);
        acc.w += __shfl_xor_sync(0xffffffffu, acc.w, o);
        den   += __shfl_xor_sync(0xffffffffu, den, o);
    }
    if (grp == 0) {
        float inv = 1.f / fmaxf(den, 1e-16f);
        float4 bb = __ldg((const float4*)&b2[c4]);
        rows[wl][c4 + 0] = acc.x * inv + bb.x;
        rows[wl][c4 + 1] = acc.y * inv + bb.y;
        rows[wl][c4 + 2] = acc.z * inv + bb.z;
        rows[wl][c4 + 3] = acc.w * inv + bb.w;
    }
    __syncthreads();
    int nb = blockIdx.x * 8;
    for (int t = tid; t < 320; t += 256) {
        int r = t / 40, o = t % 40;
        float s = __ldg(&linb[o]);
        #pragma unroll
        for (int k = 0; k < 32; k++) s += rows[r][k] * lw[k * 40 + o];
        out[(size_t)(nb + r) * 40 + o] = s;
    }
}

// ================= launch =================
extern "C" void kernel_launch(void* const* d_in, const int* in_sizes, int n_in,
                              void* d_out, int out_size) {
    const float* x0    = (const float*)d_in[0];
    const float* W1    = (const float*)d_in[1];
    const float* attS1 = (const float*)d_in[2];
    const float* attD1 = (const float*)d_in[3];
    const float* b1    = (const float*)d_in[4];
    const float* W2    = (const float*)d_in[5];
    const float* attS2 = (const float*)d_in[6];
    const float* attD2 = (const float*)d_in[7];
    const float* b2    = (const float*)d_in[8];
    const float* linW  = (const float*)d_in[9];
    const float* linb  = (const float*)d_in[10];
    const int*   ei    = (const int*)d_in[11];
    float* out = (float*)d_out;

    static cudaStream_t s_side = nullptr;
    static cudaEvent_t ev_fork = nullptr, ev_join = nullptr;
    if (!s_side) {
        cudaFuncSetAttribute(k_gemm1_mma, cudaFuncAttributeMaxDynamicSharedMemorySize, SM_G1);
        cudaFuncSetAttribute(k_gemm2_mma, cudaFuncAttributeMaxDynamicSharedMemorySize, SM_G2);
        cudaStreamCreateWithFlags(&s_side, cudaStreamNonBlocking);
        cudaEventCreateWithFlags(&ev_fork, cudaEventDisableTiming);
        cudaEventCreateWithFlags(&ev_join, cudaEventDisableTiming);
    }

    const int NBLK = (NN + 1023) / 1024;   // 98

    cudaEventRecord(ev_fork, 0);
    cudaStreamWaitEvent(s_side, ev_fork, 0);
    k_prepw1<<<128, 256>>>(W1);                                  // 1 (main)
    k_zero<<<(NN + 255) / 256, 256, 0, s_side>>>();              // 2 (side)
    k_hist<<<(EE + 255) / 256, 256, 0, s_side>>>(ei);            // 3 (side)
    k_gemm1_mma<<<(NN + 63) / 64, 256, SM_G1>>>(x0, attS1, attD1); // 4 (main)
    k_prepw2<<<32, 256>>>(W2);                                   // 5 (main, tiny)
    k_scan1<<<NBLK, 1024, 0, s_side>>>();                        // 6
    k_scan2<<<1, 128, 0, s_side>>>(NBLK);                        // 7
    k_scan3<<<NBLK, 1024, 0, s_side>>>();                        // 8
    k_scatter<<<(EE + 255) / 256, 256, 0, s_side>>>(ei);         // 9
    cudaEventRecord(ev_join, s_side);

    cudaStreamWaitEvent(0, ev_join, 0);
    k_gat1<<<(NN + 7) / 8, 256>>>(b1);
    k_gemm2_mma<<<(NN + 127) / 128, 256, SM_G2>>>(attS2, attD2);
    k_gat2<<<NN / 8, 256>>>(b2, linW, linb, out);
}